// round 4
// baseline (speedup 1.0000x reference)
#include <cuda_runtime.h>
#include <math.h>

#define B 4
#define S 4096
#define H 8
#define HD 512
#define NBS (B*S)
#define NCK 256          // chunks per batch
#define LCK (S/NCK)      // 16 timesteps per chunk
#define NCHUNK (B*NCK)   // 1024
#define LN_EPS 1e-5f

// ---- scratch (device globals) ----
__device__ float2 g_fgigh[(size_t)B*S*HD];            // (fg, igh) per (row,lane)
__device__ float  g_chunksum[(size_t)NCHUNK*HD];
__device__ float  g_chunkpref[(size_t)NCHUNK*HD];
__device__ float  g_sA[(size_t)NCHUNK*HD];
__device__ float  g_sB[(size_t)NCHUNK*HD];
__device__ float  g_cellin[(size_t)NCHUNK*HD];

__device__ __forceinline__ float sigmoidf_(float v) {
    return 1.f / (1.f + __expf(-v));
}

// KA smem column swizzle: pad 8 floats per 32-col group (conflict-free 4-way K-split reads)
__device__ __forceinline__ int cmapA(int c) { return c + ((c >> 5) << 3); }
#define ROWA 152   // cmapA(127)=151 -> 152
// KC swizzle: pad 4 floats per 16-col group (conflict-free 8-way K-split reads)
__device__ __forceinline__ int cmapC(int c) { return c + ((c >> 4) << 2); }
#define ROWC 156   // cmapC(127)=155 -> 156

// ---------------- chunk sums of x over each 16-step chunk ----------------
__global__ void k_chunksum(const float* __restrict__ x) {
    int g = blockIdx.x;                 // b*NCK + c
    int t = threadIdx.x;                // lane (h,d)
    const float* p = x + ((size_t)g * LCK) * HD + t;
    float s = 0.f;
    #pragma unroll
    for (int i = 0; i < LCK; ++i) s += p[(size_t)i * HD];
    g_chunksum[(size_t)g * HD + t] = s;
}

// ---------------- exclusive scan of chunk sums (per batch) ----------------
__global__ void k_chunkscan() {
    int b = blockIdx.x; int t = threadIdx.x;
    float run = 0.f;
    #pragma unroll 8
    for (int c = 0; c < NCK; ++c) {
        size_t i = ((size_t)(b * NCK + c)) * HD + t;
        g_chunkpref[i] = run;
        run += g_chunksum[i];
    }
}

// ============== KA: fused csum + LN + GEMM1 + gates + chunk(A,B) ==============
// 768 threads: GEMM layout j = t>>2 (col 0..191), kq = t&3 (K quarter).
__global__ void __launch_bounds__(768, 1)
k_A(const float* __restrict__ x, const float* __restrict__ Wh,
    const float* __restrict__ bh, const float* __restrict__ gamma,
    const float* __restrict__ beta) {
    __shared__ float hid[8][ROWA];
    __shared__ float h3[8][192];
    __shared__ float sb[192];
    __shared__ float sg[512], sbe[512];
    __shared__ float red_s[16], red_q[16];
    __shared__ float s_mr[2];

    int t = threadIdx.x;
    int kq = t & 3, j = t >> 2;
    int wid = t >> 5, lid = t & 31;
    float w[32];
    #pragma unroll
    for (int k = 0; k < 32; ++k) w[k] = Wh[(size_t)(kq * 32 + k) * 192 + j];
    if (t < 192) sb[t] = bh[t];
    if (t < 512) { sg[t] = gamma[t]; sbe[t] = beta[t]; }
    __syncthreads();

    int h = (t < 512) ? (t >> 6) : 0;
    int d = t & 63;

    for (int g = blockIdx.x; g < NCHUNK; g += gridDim.x) {
        int b = g >> 8, c = g & (NCK - 1);
        size_t base = ((size_t)(b * S + c * LCK)) * HD + (t < 512 ? t : 0);
        float run = 0.f, Aacc = 1.f, Bacc = 0.f, xnext = 0.f;
        if (t < 512) {
            run = g_chunkpref[(size_t)g * HD + t];
            xnext = x[base];
        }
        for (int i = 0; i < LCK; ++i) {
            float xv = xnext;
            float excl = run;
            if (t < 512) {
                if (i + 1 < LCK) xnext = x[base + (size_t)(i + 1) * HD];
                run += xv;
            }
            // --- LN stats over 512 lanes ---
            float sum = (t < 512) ? excl : 0.f;
            float sq  = (t < 512) ? excl * excl : 0.f;
            #pragma unroll
            for (int o = 16; o; o >>= 1) {
                sum += __shfl_down_sync(0xFFFFFFFFu, sum, o);
                sq  += __shfl_down_sync(0xFFFFFFFFu, sq, o);
            }
            if (lid == 0 && wid < 16) { red_s[wid] = sum; red_q[wid] = sq; }
            __syncthreads();
            if (t < 32) {
                float s1 = (t < 16) ? red_s[t] : 0.f;
                float q1 = (t < 16) ? red_q[t] : 0.f;
                #pragma unroll
                for (int o = 8; o; o >>= 1) {
                    s1 += __shfl_down_sync(0xFFFFFFFFu, s1, o);
                    q1 += __shfl_down_sync(0xFFFFFFFFu, q1, o);
                }
                if (t == 0) {
                    float m = s1 * (1.f / HD);
                    float var = q1 * (1.f / HD) - m * m;
                    s_mr[0] = m;
                    s_mr[1] = rsqrtf(var + LN_EPS);
                }
            }
            __syncthreads();
            // --- stage hid_in = concat(x, LN(csum)) ---
            if (t < 512) {
                float m = s_mr[0], rs = s_mr[1];
                hid[h][cmapA(d)]      = xv;
                hid[h][cmapA(64 + d)] = (excl - m) * rs * sg[t] + sbe[t];
            }
            __syncthreads();
            // --- GEMM 8x192x128, K split in quarters, shuffle-reduced ---
            float acc[8];
            #pragma unroll
            for (int r = 0; r < 8; ++r) {
                const float* hp = &hid[r][kq * 40];   // cmapA(kq*32) = kq*40
                float a = 0.f;
                #pragma unroll
                for (int k4 = 0; k4 < 8; ++k4) {
                    float4 hv = *(const float4*)&hp[k4 * 4];
                    a = fmaf(hv.x, w[k4 * 4 + 0], a);
                    a = fmaf(hv.y, w[k4 * 4 + 1], a);
                    a = fmaf(hv.z, w[k4 * 4 + 2], a);
                    a = fmaf(hv.w, w[k4 * 4 + 3], a);
                }
                acc[r] = a;
            }
            #pragma unroll
            for (int r = 0; r < 8; ++r) {
                float a = acc[r];
                a += __shfl_xor_sync(0xFFFFFFFFu, a, 1);
                a += __shfl_xor_sync(0xFFFFFFFFu, a, 2);
                if (kq == 0) h3[r][j] = a + sb[j];
            }
            __syncthreads();
            // --- gates + chunk (A,B) composition ---
            if (t < 512) {
                float ig  = h3[h][d];
                float fgv = h3[h][64 + d];
                float hv  = h3[h][128 + d];
                float fg  = sigmoidf_(fgv);
                float igh = sigmoidf_(ig) * fmaxf(hv, 0.f);
                g_fgigh[base + (size_t)i * HD] = make_float2(fg, igh);
                Bacc = fmaf(fg, Bacc, igh);
                Aacc *= fg;
            }
            __syncthreads();
        }
        if (t < 512) {
            g_sA[(size_t)g * HD + t] = Aacc;
            g_sB[(size_t)g * HD + t] = Bacc;
        }
    }
}

// ---------------- KB: cross-chunk affine scan -> per-chunk entry cell ----------------
__global__ void k_B(const float* __restrict__ init_cx) {
    int b = blockIdx.x; int t = threadIdx.x;
    float cell = init_cx[t];
    #pragma unroll 8
    for (int c = 0; c < NCK; ++c) {
        size_t i = ((size_t)(b * NCK + c)) * HD + t;
        g_cellin[i] = cell;
        cell = fmaf(g_sA[i], cell, g_sB[i]);
    }
}

// ============== KC: fused cell recurrence + GEMM2 + epilogue ==============
// 512 threads: GEMM layout j = t>>3 (col 0..63), kq = t&7 (K eighth).
__global__ void __launch_bounds__(512, 2)
k_C(const float* __restrict__ x, const float* __restrict__ Wo,
    const float* __restrict__ bo, float* __restrict__ out) {
    __shared__ float hid[8][ROWC];
    __shared__ float sb[64];
    int t = threadIdx.x;
    int kq = t & 7, j = t >> 3;
    float w[16];
    #pragma unroll
    for (int k = 0; k < 16; ++k) w[k] = Wo[(size_t)(kq * 16 + k) * 64 + j];
    if (t < 64) sb[t] = bo[t];
    __syncthreads();

    int h = t >> 6, d = t & 63;
    int g = blockIdx.x;
    {
        int b = g >> 8, c = g & (NCK - 1);
        size_t base = ((size_t)(b * S + c * LCK)) * HD + t;
        float cell = g_cellin[(size_t)g * HD + t];
        float2 fgn = g_fgigh[base];
        float  xn  = x[base];
        for (int i = 0; i < LCK; ++i) {
            float2 fgi = fgn;
            float  xv  = xn;
            if (i + 1 < LCK) {
                fgn = g_fgigh[base + (size_t)(i + 1) * HD];
                xn  = x[base + (size_t)(i + 1) * HD];
            }
            cell = fmaf(fgi.x, cell, fgi.y);
            hid[h][cmapC(d)]      = xv;
            hid[h][cmapC(64 + d)] = cell;
            __syncthreads();
            size_t row0 = (size_t)(base / HD + i) * 8;   // (b*S + s)*8
            #pragma unroll
            for (int r = 0; r < 8; ++r) {
                const float* hp = &hid[r][kq * 20];      // cmapC(kq*16) = kq*20
                float a = 0.f;
                #pragma unroll
                for (int k4 = 0; k4 < 4; ++k4) {
                    float4 hv = *(const float4*)&hp[k4 * 4];
                    a = fmaf(hv.x, w[k4 * 4 + 0], a);
                    a = fmaf(hv.y, w[k4 * 4 + 1], a);
                    a = fmaf(hv.z, w[k4 * 4 + 2], a);
                    a = fmaf(hv.w, w[k4 * 4 + 3], a);
                }
                a += __shfl_xor_sync(0xFFFFFFFFu, a, 1);
                a += __shfl_xor_sync(0xFFFFFFFFu, a, 2);
                a += __shfl_xor_sync(0xFFFFFFFFu, a, 4);
                if (kq == 0) {
                    float og = sigmoidf_(a + sb[j]);
                    float cv = hid[r][cmapC(64 + j)];
                    out[(row0 + r) * 64 + j] = og * cv;
                }
            }
            __syncthreads();
        }
    }
}

extern "C" void kernel_launch(void* const* d_in, const int* in_sizes, int n_in,
                              void* d_out, int out_size) {
    const float* x     = (const float*)d_in[0];   // heads_input [B,S,H,D]
    const float* Wh    = (const float*)d_in[1];   // W_hid [128,192]
    const float* bh    = (const float*)d_in[2];   // b_hid [192]
    const float* Wo    = (const float*)d_in[3];   // W_og [128,64]
    const float* bo    = (const float*)d_in[4];   // b_og [64]
    const float* gamma = (const float*)d_in[5];   // ln_gamma [H,D]
    const float* beta  = (const float*)d_in[6];   // ln_beta [H,D]
    const float* cx    = (const float*)d_in[7];   // init_cx [H,D]
    float* out = (float*)d_out;

    k_chunksum<<<NCHUNK, 512>>>(x);
    k_chunkscan<<<B, 512>>>();
    k_A<<<NCHUNK, 768>>>(x, Wh, bh, gamma, beta);
    k_B<<<B, 512>>>(cx);
    k_C<<<NCHUNK, 512>>>(x, Wo, bo, out);
}

// round 5
// speedup vs baseline: 1.1895x; 1.1895x over previous
#include <cuda_runtime.h>
#include <math.h>

#define B 4
#define S 4096
#define H 8
#define HD 512
#define NCK 256          // chunks per batch
#define LCK (S/NCK)      // 16 timesteps per chunk
#define NCHUNK (B*NCK)   // 1024
#define NG 16            // chunk groups per batch (16 chunks each)
#define LN_EPS 1e-5f

// ---- scratch (device globals) ----
__device__ float2 g_fgigh[(size_t)B*S*HD];        // (fg, igh) per (row,lane)
__device__ float  g_chunksum[(size_t)NCHUNK*HD];
__device__ float  g_chunkpref[(size_t)NCHUNK*HD];
__device__ float  g_groupsum[(size_t)B*NG*HD];
__device__ float  g_grouppref[(size_t)B*NG*HD];
__device__ float  g_sA[(size_t)NCHUNK*HD];
__device__ float  g_sB[(size_t)NCHUNK*HD];
__device__ float  g_gA[(size_t)B*NG*HD];
__device__ float  g_gB[(size_t)B*NG*HD];
__device__ float  g_gcell[(size_t)B*NG*HD];
__device__ float  g_cellin[(size_t)NCHUNK*HD];

__device__ __forceinline__ float sigmoidf_(float v) {
    return 1.f / (1.f + __expf(-v));
}

// packed f32x2 helpers (sm_103a FFMA2 path)
#define FMA_F32X2(acc, a, b) \
    asm("fma.rn.f32x2 %0, %1, %2, %0;" : "+l"(acc) : "l"(a), "l"(b))
#define PACK_F32X2(out, lo, hi) \
    asm("mov.b64 %0, {%1, %2};" : "=l"(out) : "f"(lo), "f"(hi))
#define UNPACK_F32X2(lo, hi, in) \
    asm("mov.b64 {%0, %1}, %2;" : "=f"(lo), "=f"(hi) : "l"(in))

// KA smem column swizzle: pad 8 floats per 32-col group (conflict-free 4-way K-split reads)
__device__ __forceinline__ int cmapA(int c) { return c + ((c >> 5) << 3); }
#define ROWA 152
// KC swizzle: pad 4 floats per 16-col group (conflict-free 8-way K-split reads)
__device__ __forceinline__ int cmapC(int c) { return c + ((c >> 4) << 2); }
#define ROWC 156

// ---------------- chunk sums of x over each 16-step chunk ----------------
__global__ void k_chunksum(const float* __restrict__ x) {
    int g = blockIdx.x;                 // b*NCK + c
    int t = threadIdx.x;
    const float* p = x + ((size_t)g * LCK) * HD + t;
    float s = 0.f;
    #pragma unroll
    for (int i = 0; i < LCK; ++i) s += p[(size_t)i * HD];
    g_chunksum[(size_t)g * HD + t] = s;
}

// ---------------- two-level exclusive scan of chunk sums ----------------
__global__ void k_gsum() {
    int bg = blockIdx.x;                // b*NG + G
    int t = threadIdx.x;
    size_t base = (size_t)bg * 16 * HD + t;
    float s = 0.f;
    #pragma unroll
    for (int c = 0; c < 16; ++c) s += g_chunksum[base + (size_t)c * HD];
    g_groupsum[(size_t)bg * HD + t] = s;
}
__global__ void k_gscan() {
    int b = blockIdx.x; int t = threadIdx.x;
    float run = 0.f;
    #pragma unroll
    for (int G = 0; G < NG; ++G) {
        size_t i = ((size_t)(b * NG + G)) * HD + t;
        g_grouppref[i] = run;
        run += g_groupsum[i];
    }
}
__global__ void k_cpref() {
    int bg = blockIdx.x; int t = threadIdx.x;
    float run = g_grouppref[(size_t)bg * HD + t];
    size_t base = (size_t)bg * 16 * HD + t;
    #pragma unroll
    for (int c = 0; c < 16; ++c) {
        g_chunkpref[base + (size_t)c * HD] = run;
        run += g_chunksum[base + (size_t)c * HD];
    }
}

// ============== KA: fused csum + LN + GEMM1(f32x2) + gates + chunk(A,B) ==============
// 768 threads: GEMM layout j = t>>2 (col 0..191), kq = t&3 (K quarter).
__global__ void __launch_bounds__(768, 1)
k_A(const float* __restrict__ x, const float* __restrict__ Wh,
    const float* __restrict__ bh, const float* __restrict__ gamma,
    const float* __restrict__ beta) {
    __shared__ float hid[16][ROWA];          // rows 0-7: ts i0 heads, 8-15: ts i1
    __shared__ float h3[16][192];
    __shared__ float sb[192];
    __shared__ float sg[512], sbe[512];
    __shared__ float part[16][17][2];        // [warp][ts][s,q], padded
    __shared__ float s_m[16], s_r[16];

    int t = threadIdx.x;
    int kq = t & 3, j = t >> 2;
    int wid = t >> 5, lid = t & 31;
    // pre-packed weights: wp[k2] = {W[kq*32+2k2][j], W[kq*32+2k2+1][j]}
    unsigned long long wp[16];
    {
        float wsc[32];
        #pragma unroll
        for (int k = 0; k < 32; ++k) wsc[k] = Wh[(size_t)(kq * 32 + k) * 192 + j];
        #pragma unroll
        for (int k2 = 0; k2 < 16; ++k2) PACK_F32X2(wp[k2], wsc[2*k2], wsc[2*k2+1]);
    }
    if (t < 192) sb[t] = bh[t];
    if (t < 512) { sg[t] = gamma[t]; sbe[t] = beta[t]; }
    __syncthreads();

    int h = t >> 6;          // head for t<512
    int d = t & 63;
    int g = blockIdx.x;      // chunk
    size_t base = ((size_t)g * LCK) * HD + (t < 512 ? t : 0);

    // ---- phase 0: stream x once, compute per-ts LN partials ----
    float pref0 = 0.f;
    if (t < 512) pref0 = g_chunkpref[(size_t)g * HD + t];
    if (t < 512) {
        float run = pref0;
        #pragma unroll
        for (int i = 0; i < LCK; ++i) {
            float xv = x[base + (size_t)i * HD];
            float e = run;
            float s = e, q = e * e;
            #pragma unroll
            for (int o = 16; o; o >>= 1) {
                s += __shfl_down_sync(0xFFFFFFFFu, s, o);
                q += __shfl_down_sync(0xFFFFFFFFu, q, o);
            }
            if (lid == 0) { part[wid][i][0] = s; part[wid][i][1] = q; }
            run += xv;
        }
    }
    __syncthreads();
    if (wid < 16) {          // warp wid computes stats for ts=wid
        float s = 0.f, q = 0.f;
        if (lid < 16) { s = part[lid][wid][0]; q = part[lid][wid][1]; }
        #pragma unroll
        for (int o = 8; o; o >>= 1) {
            s += __shfl_down_sync(0xFFFFFFFFu, s, o);
            q += __shfl_down_sync(0xFFFFFFFFu, q, o);
        }
        if (lid == 0) {
            float m = s * (1.f / HD);
            float var = q * (1.f / HD) - m * m;
            s_m[wid] = m;
            s_r[wid] = rsqrtf(var + LN_EPS);
        }
    }
    __syncthreads();

    // ---- stage pair 0 ----
    float run2 = pref0;
    float Aacc = 1.f, Bacc = 0.f;
    if (t < 512) {
        float x0 = x[base];
        float x1 = x[base + HD];
        float e0 = run2; run2 += x0;
        float e1 = run2; run2 += x1;
        hid[h][cmapA(d)]        = x0;
        hid[h][cmapA(64 + d)]   = (e0 - s_m[0]) * s_r[0] * sg[t] + sbe[t];
        hid[8+h][cmapA(d)]      = x1;
        hid[8+h][cmapA(64 + d)] = (e1 - s_m[1]) * s_r[1] * sg[t] + sbe[t];
    }
    __syncthreads();

    for (int p = 0; p < 8; ++p) {
        // ---- GEMM 16 rows x 192 x 128, f32x2, K-quarter split ----
        #pragma unroll
        for (int grp = 0; grp < 2; ++grp) {
            unsigned long long acc2[8];
            #pragma unroll
            for (int r = 0; r < 8; ++r) acc2[r] = 0ULL;
            #pragma unroll
            for (int r = 0; r < 8; ++r) {
                const ulonglong2* hp =
                    (const ulonglong2*)&hid[grp*8 + r][kq * 40];  // cmapA(kq*32)
                #pragma unroll
                for (int k4 = 0; k4 < 8; ++k4) {
                    ulonglong2 hv = hp[k4];
                    FMA_F32X2(acc2[r], hv.x, wp[2*k4]);
                    FMA_F32X2(acc2[r], hv.y, wp[2*k4+1]);
                }
            }
            #pragma unroll
            for (int r = 0; r < 8; ++r) {
                float lo, hi;
                UNPACK_F32X2(lo, hi, acc2[r]);
                float a = lo + hi;
                a += __shfl_xor_sync(0xFFFFFFFFu, a, 1);
                a += __shfl_xor_sync(0xFFFFFFFFu, a, 2);
                if (kq == 0) h3[grp*8 + r][j] = a + sb[j];
            }
        }
        __syncthreads();
        // ---- gates for pair p + stage pair p+1 ----
        if (t < 512) {
            int i0 = 2 * p;
            {
                float ig  = h3[h][d];
                float fgv = h3[h][64 + d];
                float hv  = h3[h][128 + d];
                float fg  = sigmoidf_(fgv);
                float igh = sigmoidf_(ig) * fmaxf(hv, 0.f);
                g_fgigh[base + (size_t)i0 * HD] = make_float2(fg, igh);
                Bacc = fmaf(fg, Bacc, igh);
                Aacc *= fg;
            }
            {
                float ig  = h3[8+h][d];
                float fgv = h3[8+h][64 + d];
                float hv  = h3[8+h][128 + d];
                float fg  = sigmoidf_(fgv);
                float igh = sigmoidf_(ig) * fmaxf(hv, 0.f);
                g_fgigh[base + (size_t)(i0+1) * HD] = make_float2(fg, igh);
                Bacc = fmaf(fg, Bacc, igh);
                Aacc *= fg;
            }
            if (p < 7) {
                int i2 = 2*p + 2;
                float x0 = x[base + (size_t)i2 * HD];
                float x1 = x[base + (size_t)(i2+1) * HD];
                float e0 = run2; run2 += x0;
                float e1 = run2; run2 += x1;
                hid[h][cmapA(d)]        = x0;
                hid[h][cmapA(64 + d)]   = (e0 - s_m[i2])   * s_r[i2]   * sg[t] + sbe[t];
                hid[8+h][cmapA(d)]      = x1;
                hid[8+h][cmapA(64 + d)] = (e1 - s_m[i2+1]) * s_r[i2+1] * sg[t] + sbe[t];
            }
        }
        __syncthreads();
    }
    if (t < 512) {
        g_sA[(size_t)g * HD + t] = Aacc;
        g_sB[(size_t)g * HD + t] = Bacc;
    }
}

// ---------------- two-level cross-chunk affine scan ----------------
__global__ void k_b1() {
    int bg = blockIdx.x; int t = threadIdx.x;
    size_t base = (size_t)bg * 16 * HD + t;
    float Ag = 1.f, Bg = 0.f;
    #pragma unroll
    for (int c = 0; c < 16; ++c) {
        float a = g_sA[base + (size_t)c * HD];
        float b = g_sB[base + (size_t)c * HD];
        Bg = fmaf(a, Bg, b);
        Ag = a * Ag;
    }
    g_gA[(size_t)bg * HD + t] = Ag;
    g_gB[(size_t)bg * HD + t] = Bg;
}
__global__ void k_b2(const float* __restrict__ init_cx) {
    int b = blockIdx.x; int t = threadIdx.x;
    float cell = init_cx[t];
    #pragma unroll
    for (int G = 0; G < NG; ++G) {
        size_t i = ((size_t)(b * NG + G)) * HD + t;
        g_gcell[i] = cell;
        cell = fmaf(g_gA[i], cell, g_gB[i]);
    }
}
__global__ void k_b3() {
    int bg = blockIdx.x; int t = threadIdx.x;
    float cell = g_gcell[(size_t)bg * HD + t];
    size_t base = (size_t)bg * 16 * HD + t;
    #pragma unroll
    for (int c = 0; c < 16; ++c) {
        g_cellin[base + (size_t)c * HD] = cell;
        cell = fmaf(g_sA[base + (size_t)c * HD], cell,
                    g_sB[base + (size_t)c * HD]);
    }
}

// ============== KC: fused cell recurrence + GEMM2 + epilogue (paired ts) ==============
__global__ void __launch_bounds__(512, 2)
k_C(const float* __restrict__ x, const float* __restrict__ Wo,
    const float* __restrict__ bo, float* __restrict__ out) {
    __shared__ float hid[16][ROWC];
    __shared__ float sb[64];
    int t = threadIdx.x;
    int kq = t & 7, j = t >> 3;
    float w[16];
    #pragma unroll
    for (int k = 0; k < 16; ++k) w[k] = Wo[(size_t)(kq * 16 + k) * 64 + j];
    if (t < 64) sb[t] = bo[t];
    __syncthreads();

    int h = t >> 6, d = t & 63;
    int g = blockIdx.x;
    size_t base = ((size_t)g * LCK) * HD + t;
    size_t srow0 = (size_t)g * LCK;       // global (b*S+s) for first ts
    float cell = g_cellin[(size_t)g * HD + t];

    for (int p = 0; p < 8; ++p) {
        int i0 = 2 * p;
        float2 f0 = g_fgigh[base + (size_t)i0 * HD];
        float2 f1 = g_fgigh[base + (size_t)(i0+1) * HD];
        float  x0 = x[base + (size_t)i0 * HD];
        float  x1 = x[base + (size_t)(i0+1) * HD];
        cell = fmaf(f0.x, cell, f0.y);
        float c0 = cell;
        cell = fmaf(f1.x, cell, f1.y);
        float c1 = cell;
        hid[h][cmapC(d)]        = x0;
        hid[h][cmapC(64 + d)]   = c0;
        hid[8+h][cmapC(d)]      = x1;
        hid[8+h][cmapC(64 + d)] = c1;
        __syncthreads();
        #pragma unroll
        for (int r = 0; r < 16; ++r) {
            const float* hp = &hid[r][kq * 20];   // cmapC(kq*16)
            float a = 0.f;
            #pragma unroll
            for (int k4 = 0; k4 < 4; ++k4) {
                float4 hv = *(const float4*)&hp[k4 * 4];
                a = fmaf(hv.x, w[k4 * 4 + 0], a);
                a = fmaf(hv.y, w[k4 * 4 + 1], a);
                a = fmaf(hv.z, w[k4 * 4 + 2], a);
                a = fmaf(hv.w, w[k4 * 4 + 3], a);
            }
            a += __shfl_xor_sync(0xFFFFFFFFu, a, 1);
            a += __shfl_xor_sync(0xFFFFFFFFu, a, 2);
            a += __shfl_xor_sync(0xFFFFFFFFu, a, 4);
            if (kq == 0) {
                float og = sigmoidf_(a + sb[j]);
                float cv = hid[r][cmapC(64 + j)];
                int ts = i0 + (r >> 3);
                int head = r & 7;
                out[((srow0 + ts) * 8 + head) * 64 + j] = og * cv;
            }
        }
        __syncthreads();
    }
}

extern "C" void kernel_launch(void* const* d_in, const int* in_sizes, int n_in,
                              void* d_out, int out_size) {
    const float* x     = (const float*)d_in[0];   // heads_input [B,S,H,D]
    const float* Wh    = (const float*)d_in[1];   // W_hid [128,192]
    const float* bh    = (const float*)d_in[2];   // b_hid [192]
    const float* Wo    = (const float*)d_in[3];   // W_og [128,64]
    const float* bo    = (const float*)d_in[4];   // b_og [64]
    const float* gamma = (const float*)d_in[5];   // ln_gamma [H,D]
    const float* beta  = (const float*)d_in[6];   // ln_beta [H,D]
    const float* cx    = (const float*)d_in[7];   // init_cx [H,D]
    float* out = (float*)d_out;

    k_chunksum<<<NCHUNK, 512>>>(x);
    k_gsum<<<B*NG, 512>>>();
    k_gscan<<<B, 512>>>();
    k_cpref<<<B*NG, 512>>>();
    k_A<<<NCHUNK, 768>>>(x, Wh, bh, gamma, beta);
    k_b1<<<B*NG, 512>>>();
    k_b2<<<B, 512>>>(cx);
    k_b3<<<B*NG, 512>>>();
    k_C<<<NCHUNK, 512>>>(x, Wo, bo, out);
}

// round 8
// speedup vs baseline: 1.2544x; 1.0545x over previous
#include <cuda_runtime.h>
#include <math.h>

#define B 4
#define S 4096
#define H 8
#define HD 512
#define NCK 256          // chunks per batch
#define LCK (S/NCK)      // 16 timesteps per chunk
#define NCHUNK (B*NCK)   // 1024
#define NG 16            // chunk groups per batch (16 chunks each)
#define LN_EPS 1e-5f

// ---- scratch (device globals) ----
__device__ float2 g_fgigh[(size_t)B*S*HD];
__device__ float  g_chunksum[(size_t)NCHUNK*HD];
__device__ float  g_chunkpref[(size_t)NCHUNK*HD];
__device__ float  g_groupsum[(size_t)B*NG*HD];
__device__ float  g_grouppref[(size_t)B*NG*HD];
__device__ float  g_sA[(size_t)NCHUNK*HD];
__device__ float  g_sB[(size_t)NCHUNK*HD];
__device__ float  g_gA[(size_t)B*NG*HD];
__device__ float  g_gB[(size_t)B*NG*HD];
__device__ float  g_gcell[(size_t)B*NG*HD];
__device__ float  g_cellin[(size_t)NCHUNK*HD];

__device__ __forceinline__ float sigmoidf_(float v) {
    return 1.f / (1.f + __expf(-v));
}

// packed f32x2 helpers (sm_103a FFMA2 path)
#define FMA_F32X2(acc, a, b) \
    asm("fma.rn.f32x2 %0, %1, %2, %0;" : "+l"(acc) : "l"(a), "l"(b))
#define PACK_F32X2(out, lo, hi) \
    asm("mov.b64 %0, {%1, %2};" : "=l"(out) : "f"(lo), "f"(hi))
#define UNPACK_F32X2(lo, hi, in) \
    asm("mov.b64 {%0, %1}, %2;" : "=f"(lo), "=f"(hi) : "l"(in))

// KA swizzle: pad 8 floats per 32-col group (4-way K-split conflict-free)
__device__ __forceinline__ int cmapA(int c) { return c + ((c >> 5) << 3); }
#define ROWA 152
// KC swizzle: pad 4 floats per 16-col group (8-way K-split conflict-free)
__device__ __forceinline__ int cmapC(int c) { return c + ((c >> 4) << 2); }
#define ROWC 156

// k_A dynamic smem layout (floats)
#define OF_HID  0                       // [128][ROWA]
#define OF_H3   (128*ROWA)              // [128][192]
#define OF_SG   (OF_H3 + 128*192)       // [512]
#define OF_SBE  (OF_SG + 512)           // [512]
#define OF_SB   (OF_SBE + 512)          // [192]
#define OF_PART (OF_SB + 192)           // [16][34]  (warp-major, padded)
#define OF_SMR  (OF_PART + 16*34)       // [32]: m[16], r[16]
#define SMEM_A_FLOATS (OF_SMR + 32)
#define SMEM_A_BYTES  (SMEM_A_FLOATS * 4)

// ---------------- chunk sums ----------------
__global__ void k_chunksum(const float* __restrict__ x) {
    int g = blockIdx.x;
    int t = threadIdx.x;
    const float* p = x + ((size_t)g * LCK) * HD + t;
    float s = 0.f;
    #pragma unroll
    for (int i = 0; i < LCK; ++i) s += p[(size_t)i * HD];
    g_chunksum[(size_t)g * HD + t] = s;
}

// ---------------- two-level exclusive scan of chunk sums ----------------
__global__ void k_gsum() {
    int bg = blockIdx.x; int t = threadIdx.x;
    size_t base = (size_t)bg * 16 * HD + t;
    float s = 0.f;
    #pragma unroll
    for (int c = 0; c < 16; ++c) s += g_chunksum[base + (size_t)c * HD];
    g_groupsum[(size_t)bg * HD + t] = s;
}
__global__ void k_gscan() {
    int b = blockIdx.x; int t = threadIdx.x;
    float run = 0.f;
    #pragma unroll
    for (int G = 0; G < NG; ++G) {
        size_t i = ((size_t)(b * NG + G)) * HD + t;
        g_grouppref[i] = run;
        run += g_groupsum[i];
    }
}
__global__ void k_cpref() {
    int bg = blockIdx.x; int t = threadIdx.x;
    float run = g_grouppref[(size_t)bg * HD + t];
    size_t base = (size_t)bg * 16 * HD + t;
    #pragma unroll
    for (int c = 0; c < 16; ++c) {
        g_chunkpref[base + (size_t)c * HD] = run;
        run += g_chunksum[base + (size_t)c * HD];
    }
}

// ============== KA: full-chunk staged GEMM1 (4 barriers/chunk) ==============
__global__ void __launch_bounds__(768, 1)
k_A(const float* __restrict__ x, const float* __restrict__ Wh,
    const float* __restrict__ bh, const float* __restrict__ gamma,
    const float* __restrict__ beta) {
    extern __shared__ float sm[];
    float* hid  = sm + OF_HID;    // [128][ROWA]
    float* h3   = sm + OF_H3;     // [128][192]
    float* sg   = sm + OF_SG;
    float* sbe  = sm + OF_SBE;
    float* sb   = sm + OF_SB;
    float* part = sm + OF_PART;   // [warp][2*ts + {0,1}] stride 34
    float* smr  = sm + OF_SMR;    // m[0..15], r[16..31]

    int t = threadIdx.x;
    int kq = t & 3, j = t >> 2;
    int wid = t >> 5, lid = t & 31;

    unsigned long long wp[16];
    {
        float wsc[32];
        #pragma unroll
        for (int k = 0; k < 32; ++k) wsc[k] = Wh[(size_t)(kq * 32 + k) * 192 + j];
        #pragma unroll
        for (int k2 = 0; k2 < 16; ++k2) PACK_F32X2(wp[k2], wsc[2*k2], wsc[2*k2+1]);
    }
    if (t < 192) sb[t] = bh[t];
    if (t < 512) { sg[t] = gamma[t]; sbe[t] = beta[t]; }

    int h = t >> 6, d = t & 63;
    int g = blockIdx.x;
    size_t base = ((size_t)g * LCK) * HD + (t < 512 ? t : 0);

    // ---- phase A: stream x, stage x + excl-csum, per-ts LN partials ----
    if (t < 512) {
        float run = g_chunkpref[(size_t)g * HD + t];
        #pragma unroll
        for (int i = 0; i < LCK; ++i) {
            float xv = x[base + (size_t)i * HD];
            float e = run; run += xv;
            hid[(i*8 + h) * ROWA + cmapA(d)]      = xv;
            hid[(i*8 + h) * ROWA + cmapA(64 + d)] = e;   // raw excl (transformed later)
            float s = e, q = e * e;
            #pragma unroll
            for (int o = 16; o; o >>= 1) {
                s += __shfl_down_sync(0xFFFFFFFFu, s, o);
                q += __shfl_down_sync(0xFFFFFFFFu, q, o);
            }
            if (lid == 0) { part[wid * 34 + 2*i] = s; part[wid * 34 + 2*i + 1] = q; }
        }
    }
    __syncthreads();
    if (wid < 16) {                    // warp wid -> stats for ts=wid
        float s = 0.f, q = 0.f;
        if (lid < 16) { s = part[lid * 34 + 2*wid]; q = part[lid * 34 + 2*wid + 1]; }
        #pragma unroll
        for (int o = 8; o; o >>= 1) {
            s += __shfl_down_sync(0xFFFFFFFFu, s, o);
            q += __shfl_down_sync(0xFFFFFFFFu, q, o);
        }
        if (lid == 0) {
            float m = s * (1.f / HD);
            float var = q * (1.f / HD) - m * m;
            smr[wid]      = m;
            smr[16 + wid] = rsqrtf(var + LN_EPS);
        }
    }
    __syncthreads();
    // ---- apply LN in place ----
    if (t < 512) {
        float gv = sg[t], bv = sbe[t];
        #pragma unroll
        for (int i = 0; i < LCK; ++i) {
            int idx = (i*8 + h) * ROWA + cmapA(64 + d);
            float e = hid[idx];
            hid[idx] = (e - smr[i]) * smr[16 + i] * gv + bv;
        }
    }
    __syncthreads();

    // ---- GEMM: 128 rows x 192 x 128, barrier-free stretch ----
    #pragma unroll
    for (int grp = 0; grp < 16; ++grp) {
        unsigned long long acc2[8];
        #pragma unroll
        for (int r = 0; r < 8; ++r) acc2[r] = 0ULL;
        #pragma unroll
        for (int r = 0; r < 8; ++r) {
            const ulonglong2* hp =
                (const ulonglong2*)&hid[(grp*8 + r) * ROWA + kq * 40];
            #pragma unroll
            for (int k4 = 0; k4 < 8; ++k4) {
                ulonglong2 hv = hp[k4];
                FMA_F32X2(acc2[r], hv.x, wp[2*k4]);
                FMA_F32X2(acc2[r], hv.y, wp[2*k4+1]);
            }
        }
        #pragma unroll
        for (int r = 0; r < 8; ++r) {
            float lo, hi;
            UNPACK_F32X2(lo, hi, acc2[r]);
            float a = lo + hi;
            a += __shfl_xor_sync(0xFFFFFFFFu, a, 1);
            a += __shfl_xor_sync(0xFFFFFFFFu, a, 2);
            if (kq == 0) h3[(grp*8 + r) * 192 + j] = a + sb[j];
        }
    }
    __syncthreads();

    // ---- gates + chunk (A,B) ----
    if (t < 512) {
        float Aacc = 1.f, Bacc = 0.f;
        #pragma unroll
        for (int i = 0; i < LCK; ++i) {
            const float* hr = &h3[(i*8 + h) * 192];
            float ig  = hr[d];
            float fgv = hr[64 + d];
            float hv  = hr[128 + d];
            float fg  = sigmoidf_(fgv);
            float igh = sigmoidf_(ig) * fmaxf(hv, 0.f);
            g_fgigh[base + (size_t)i * HD] = make_float2(fg, igh);
            Bacc = fmaf(fg, Bacc, igh);
            Aacc *= fg;
        }
        g_sA[(size_t)g * HD + t] = Aacc;
        g_sB[(size_t)g * HD + t] = Bacc;
    }
}

// ---------------- two-level cross-chunk affine scan ----------------
__global__ void k_b1() {
    int bg = blockIdx.x; int t = threadIdx.x;
    size_t base = (size_t)bg * 16 * HD + t;
    float Ag = 1.f, Bg = 0.f;
    #pragma unroll
    for (int c = 0; c < 16; ++c) {
        float a = g_sA[base + (size_t)c * HD];
        float b = g_sB[base + (size_t)c * HD];
        Bg = fmaf(a, Bg, b);
        Ag = a * Ag;
    }
    g_gA[(size_t)bg * HD + t] = Ag;
    g_gB[(size_t)bg * HD + t] = Bg;
}
__global__ void k_b2(const float* __restrict__ init_cx) {
    int b = blockIdx.x; int t = threadIdx.x;
    float cell = init_cx[t];
    #pragma unroll
    for (int G = 0; G < NG; ++G) {
        size_t i = ((size_t)(b * NG + G)) * HD + t;
        g_gcell[i] = cell;
        cell = fmaf(g_gA[i], cell, g_gB[i]);
    }
}
__global__ void k_b3() {
    int bg = blockIdx.x; int t = threadIdx.x;
    float cell = g_gcell[(size_t)bg * HD + t];
    size_t base = (size_t)bg * 16 * HD + t;
    #pragma unroll
    for (int c = 0; c < 16; ++c) {
        g_cellin[base + (size_t)c * HD] = cell;
        cell = fmaf(g_sA[base + (size_t)c * HD], cell,
                    g_sB[base + (size_t)c * HD]);
    }
}

// ============== KC: half-chunk staged GEMM2 + epilogue (occ 2, f32x2) ==============
__global__ void __launch_bounds__(512, 2)
k_C(const float* __restrict__ x, const float* __restrict__ Wo,
    const float* __restrict__ bo, float* __restrict__ out) {
    __shared__ float hid[64][ROWC];
    __shared__ float sb[64];
    int t = threadIdx.x;
    int kq = t & 7, j = t >> 3;
    unsigned long long wp[8];
    {
        float wsc[16];
        #pragma unroll
        for (int k = 0; k < 16; ++k) wsc[k] = Wo[(size_t)(kq * 16 + k) * 64 + j];
        #pragma unroll
        for (int k2 = 0; k2 < 8; ++k2) PACK_F32X2(wp[k2], wsc[2*k2], wsc[2*k2+1]);
    }
    if (t < 64) sb[t] = bo[t];

    int h = t >> 6, d = t & 63;
    int g = blockIdx.x;
    size_t base = ((size_t)g * LCK) * HD + t;
    size_t srow0 = (size_t)g * LCK;
    float cell = g_cellin[(size_t)g * HD + t];
    __syncthreads();

    for (int p = 0; p < 2; ++p) {
        int i0 = p * 8;
        // stage 8 ts: cell recurrence + hid
        #pragma unroll
        for (int i = 0; i < 8; ++i) {
            float2 f = g_fgigh[base + (size_t)(i0 + i) * HD];
            float xv = x[base + (size_t)(i0 + i) * HD];
            cell = fmaf(f.x, cell, f.y);
            hid[i*8 + h][cmapC(d)]      = xv;
            hid[i*8 + h][cmapC(64 + d)] = cell;
        }
        __syncthreads();
        // GEMM 64 rows x 64 x 128 + fused epilogue, barrier-free
        #pragma unroll
        for (int grp = 0; grp < 8; ++grp) {
            unsigned long long acc2[8];
            #pragma unroll
            for (int r = 0; r < 8; ++r) acc2[r] = 0ULL;
            #pragma unroll
            for (int r = 0; r < 8; ++r) {
                const ulonglong2* hp =
                    (const ulonglong2*)&hid[grp*8 + r][kq * 20];
                #pragma unroll
                for (int k4 = 0; k4 < 4; ++k4) {
                    ulonglong2 hv = hp[k4];
                    FMA_F32X2(acc2[r], hv.x, wp[2*k4]);
                    FMA_F32X2(acc2[r], hv.y, wp[2*k4+1]);
                }
            }
            #pragma unroll
            for (int r = 0; r < 8; ++r) {
                float lo, hi;
                UNPACK_F32X2(lo, hi, acc2[r]);
                float a = lo + hi;
                a += __shfl_xor_sync(0xFFFFFFFFu, a, 1);
                a += __shfl_xor_sync(0xFFFFFFFFu, a, 2);
                a += __shfl_xor_sync(0xFFFFFFFFu, a, 4);
                if (kq == 0) {
                    int row = grp*8 + r;           // ts_local*8 + head
                    float og = sigmoidf_(a + sb[j]);
                    float cv = hid[row][cmapC(64 + j)];
                    int ts = i0 + (row >> 3);
                    int head = row & 7;
                    out[((srow0 + ts) * 8 + head) * 64 + j] = og * cv;
                }
            }
        }
        __syncthreads();
    }
}

extern "C" void kernel_launch(void* const* d_in, const int* in_sizes, int n_in,
                              void* d_out, int out_size) {
    const float* x     = (const float*)d_in[0];
    const float* Wh    = (const float*)d_in[1];
    const float* bh    = (const float*)d_in[2];
    const float* Wo    = (const float*)d_in[3];
    const float* bo    = (const float*)d_in[4];
    const float* gamma = (const float*)d_in[5];
    const float* beta  = (const float*)d_in[6];
    const float* cx    = (const float*)d_in[7];
    float* out = (float*)d_out;

    cudaFuncSetAttribute(k_A, cudaFuncAttributeMaxDynamicSharedMemorySize,
                         SMEM_A_BYTES);

    k_chunksum<<<NCHUNK, 512>>>(x);
    k_gsum<<<B*NG, 512>>>();
    k_gscan<<<B, 512>>>();
    k_cpref<<<B*NG, 512>>>();
    k_A<<<NCHUNK, 768, SMEM_A_BYTES>>>(x, Wh, bh, gamma, beta);
    k_b1<<<B*NG, 512>>>();
    k_b2<<<B, 512>>>(cx);
    k_b3<<<B*NG, 512>>>();
    k_C<<<NCHUNK, 512>>>(x, Wo, bo, out);
}